// round 7
// baseline (speedup 1.0000x reference)
#include <cuda_runtime.h>
#include <math.h>

#define NB   8
#define ND   512
#define NDIM 2
#define NCH  3
#define NMIX 4
#define HD   128

typedef unsigned long long u64;

// feature partials: [half][bk][a][m]  (bk = b*3+k), m contiguous
__device__ float g_feat2[2 * NB * NCH * ND * NMIX];
// h0 scratch: [b][k*128+j]
__device__ float g_h0[NB * NCH * HD];

__device__ __forceinline__ float ex2_approx(float x) {
    float r;
    asm("ex2.approx.ftz.f32 %0, %1;" : "=f"(r) : "f"(x));
    return r;
}
__device__ __forceinline__ u64 fma2(u64 a, u64 b, u64 c) {
    u64 d; asm("fma.rn.f32x2 %0, %1, %2, %3;" : "=l"(d) : "l"(a), "l"(b), "l"(c)); return d;
}
__device__ __forceinline__ u64 add2(u64 a, u64 b) {
    u64 d; asm("add.rn.f32x2 %0, %1, %2;" : "=l"(d) : "l"(a), "l"(b)); return d;
}
__device__ __forceinline__ u64 mul2(u64 a, u64 b) {
    u64 d; asm("mul.rn.f32x2 %0, %1, %2;" : "=l"(d) : "l"(a), "l"(b)); return d;
}
__device__ __forceinline__ u64 pack2(float lo, float hi) {
    u64 d; asm("mov.b64 %0, {%1, %2};" : "=l"(d) : "f"(lo), "f"(hi)); return d;
}
__device__ __forceinline__ void unpack2(u64 v, float& lo, float& hi) {
    asm("mov.b64 {%0, %1}, %2;" : "=f"(lo), "=f"(hi) : "l"(v));
}

// ---------------------------------------------------------------------------
// Kernel 1: fused pairwise SM-kernel + contraction, f32x2-packed inner loop.
// Grid: 96 combos (b,k,m) x 8 a-slices x 2 c-halves = 1536 blocks, 64 thr.
// ---------------------------------------------------------------------------
__global__ __launch_bounds__(64) void k1_feature(
    const float* __restrict__ xc, const float* __restrict__ yc,
    const float* __restrict__ mu, const float* __restrict__ istd)
{
    // per-c-pair SoA: sA = {u0_lo,u0_hi,u1_lo,u1_hi}, sB = {ez_lo,ez_hi,yc_lo,yc_hi}
    __shared__ float4 sA[128];
    __shared__ float4 sB[128];
    __shared__ float2 sY[128];   // {ys_lo, ys_hi}

    const int bx    = blockIdx.x;
    const int half  = bx & 1;          // c half
    const int slice = (bx >> 1) & 7;   // a slice of 64
    const int combo = bx >> 4;         // 0..95
    const int m     = combo & 3;
    const int bk    = combo >> 2;      // b*3+k
    const int k     = bk % 3;
    const int b     = bk / 3;
    const int c0    = half * 256;

    const float AL2  = 19.739208802178716f * 1.4426950408889634f; // 0.5*(2pi)^2*log2e
    const float PI2f = 6.2831853071795864f;

    const float is0 = istd[m * 2 + 0], is1 = istd[m * 2 + 1];
    const float m0  = mu[m * 2 + 0],  m1  = mu[m * 2 + 1];

    const int tid = threadIdx.x;

    // ---- a-side loads early ----
    const int a  = slice * 64 + tid;
    const int ai = b * ND + a;
    const float ax0 = xc[ai * 6 + k];
    const float ax1 = xc[ai * 6 + 3 + k];
    const float ya  = yc[ai * 3 + k];

    // ---- c-side precompute for this half (256 c's) ----
    float* Af = reinterpret_cast<float*>(sA);
    float* Bf = reinterpret_cast<float*>(sB);
    float* Yf = reinterpret_cast<float*>(sY);
#pragma unroll
    for (int cl = tid; cl < 256; cl += 64) {
        const int c  = c0 + cl;
        const int gi = b * ND + c;
        float x0 = xc[gi * 6 + k];
        float x1 = xc[gi * 6 + 3 + k];
        float y  = yc[gi * 3 + k];
        float u0 = x0 * is0, u1 = x1 * is1;
        float e  = u0 * u0 + u1 * u1;
        float p  = x0 * m0 + x1 * m1;
        p -= rintf(p);
        float s, cph;
        __sincosf(PI2f * p, &s, &cph);
        const int pr = cl >> 1, h = cl & 1;
        Af[pr * 4 + h]     = u0;
        Af[pr * 4 + 2 + h] = u1;
        Bf[pr * 4 + h]     = -AL2 * e;
        Bf[pr * 4 + 2 + h] = y * cph;
        Yf[pr * 2 + h]     = y * s;
    }

    // ---- a-side per-thread values (packed duplicates) ----
    float ua0 = ax0 * is0, ua1 = ax1 * is1;
    float wa0 = 2.0f * AL2 * ua0;
    float wa1 = 2.0f * AL2 * ua1;
    float base = -AL2 * (ua0 * ua0 + ua1 * ua1);
    float p = ax0 * m0 + ax1 * m1;
    p -= rintf(p);
    float sa, ca;
    __sincosf(PI2f * p, &sa, &ca);

    const u64 wa0p  = pack2(wa0, wa0);
    const u64 wa1p  = pack2(wa1, wa1);
    const u64 basep = pack2(base, base);
    const u64 sap   = pack2(sa, sa);
    const u64 cap   = pack2(ca, ca);

    __syncthreads();

    const ulonglong2* Au = reinterpret_cast<const ulonglong2*>(sA);
    const ulonglong2* Bu = reinterpret_cast<const ulonglong2*>(sB);
    const u64*        Yu = reinterpret_cast<const u64*>(sY);

    u64 acc = 0;   // packed {acc_even, acc_odd}, bits of 0.0f
#pragma unroll 8
    for (int i = 0; i < 128; i++) {
        ulonglong2 va = Au[i];      // .x = u0 pair, .y = u1 pair
        ulonglong2 vb = Bu[i];      // .x = ez pair, .y = yc pair
        u64 yp = Yu[i];             // ys pair
        u64 t = fma2(wa0p, va.x, vb.x);
        t = fma2(wa1p, va.y, t);
        t = add2(t, basep);
        float tl, th;
        unpack2(t, tl, th);
        u64 ep = pack2(ex2_approx(tl), ex2_approx(th));
        u64 q  = fma2(sap, yp, mul2(cap, vb.y));
        acc = fma2(ep, q, acc);
    }
    float alo, ahi;
    unpack2(acc, alo, ahi);
    float total = alo + ahi;
    if ((a >> 8) == half) total += 0.0001f * ya;   // ZITTER * eye

    g_feat2[((half * (NB * NCH) + bk) * ND + a) * 4 + m] = total;
}

// ---------------------------------------------------------------------------
// Kernel 2a: layer-1 + relu + mean over a. One warp per (b, output).
// Grid: 384 blocks x 256 threads; block covers 8 outputs of the same b.
// ---------------------------------------------------------------------------
__global__ __launch_bounds__(256) void k2a_layer1(
    const float* __restrict__ yc,
    const float* __restrict__ w1, const float* __restrict__ b1)
{
    __shared__ float sy[ND * NCH];   // 6 KB

    const int b = blockIdx.x / 48;   // 48 blocks per batch
    const int tid = threadIdx.x;

    for (int i = tid; i < ND * NCH; i += 256)
        sy[i] = yc[b * ND * NCH + i];
    __syncthreads();

    const int warp = tid >> 5;
    const int lane = tid & 31;
    const int o    = (blockIdx.x * 8 + warp) % (NCH * HD);  // k*128 + j
    const int k    = o / HD;
    const int j    = o % HD;

    const float wj0 = w1[j * 5 + 0], wj1 = w1[j * 5 + 1], wj2 = w1[j * 5 + 2];
    const float wj3 = w1[j * 5 + 3], wj4 = w1[j * 5 + 4], bj = b1[j];

    const float4* gF = reinterpret_cast<const float4*>(g_feat2);
    const int base0 = (b * NCH + k) * ND;                   // half 0
    const int base1 = (NB * NCH + b * NCH + k) * ND;        // half 1

    float acc = 0.0f;
#pragma unroll
    for (int i = 0; i < ND / 32; i++) {
        const int a = i * 32 + lane;
        float4 f0 = gF[base0 + a];
        float4 f1 = gF[base1 + a];
        float  y  = sy[a * 3 + k];
        float fx = f0.x + f1.x, fy = f0.y + f1.y;
        float fz = f0.z + f1.z, fw = f0.w + f1.w;
        float v = fmaf(fx, wj0,
                  fmaf(fy, wj1,
                  fmaf(fz, wj2,
                  fmaf(fw, wj3,
                  fmaf(y,  wj4, bj)))));
        acc += fmaxf(v, 0.0f);
    }
#pragma unroll
    for (int s = 16; s > 0; s >>= 1)
        acc += __shfl_xor_sync(0xFFFFFFFFu, acc, s);

    if (lane == 0)
        g_h0[b * (NCH * HD) + o] = acc * (1.0f / (float)ND);
}

// ---------------------------------------------------------------------------
// Kernel 2b: 3 hidden GEMVs + head. 8 blocks x 512 threads, 4 threads/output.
// tid = j*4 + q ; quarters reduced via shfl_xor(1),(2) (same warp).
// ---------------------------------------------------------------------------
template <int N4>
__device__ __forceinline__ float dot_quarter(const float4* wr, const float4* hv) {
    float a0 = 0.0f, a1 = 0.0f;
#pragma unroll
    for (int i = 0; i < N4; i++) {
        float4 w = wr[i], h = hv[i];
        if (i & 1)
            a1 = fmaf(w.x, h.x, fmaf(w.y, h.y, fmaf(w.z, h.z, fmaf(w.w, h.w, a1))));
        else
            a0 = fmaf(w.x, h.x, fmaf(w.y, h.y, fmaf(w.z, h.z, fmaf(w.w, h.w, a0))));
    }
    return a0 + a1;
}

__global__ __launch_bounds__(512) void k2b_mlp(
    const float* __restrict__ w2, const float* __restrict__ b2,
    const float* __restrict__ w3, const float* __restrict__ b3,
    const float* __restrict__ w4, const float* __restrict__ b4,
    const float* __restrict__ w5, const float* __restrict__ b5,
    float* __restrict__ out)
{
    __shared__ __align__(16) float h0[NCH * HD];
    __shared__ __align__(16) float h1[HD];
    __shared__ __align__(16) float h2[HD];
    __shared__ __align__(16) float h3[HD];

    const int b   = blockIdx.x;
    const int tid = threadIdx.x;
    const int j   = tid >> 2;
    const int q   = tid & 3;

    for (int i = tid; i < NCH * HD; i += 512)
        h0[i] = g_h0[b * (NCH * HD) + i];
    __syncthreads();

    // ---- 384 -> 128 : quarter = 96 floats = 24 float4 ----
    {
        const float4* wr = reinterpret_cast<const float4*>(w2 + j * (NCH * HD) + q * 96);
        const float4* hv = reinterpret_cast<const float4*>(h0 + q * 96);
        float acc = dot_quarter<24>(wr, hv);
        acc += __shfl_xor_sync(0xFFFFFFFFu, acc, 1);
        acc += __shfl_xor_sync(0xFFFFFFFFu, acc, 2);
        if (q == 0) h1[j] = fmaxf(acc + b2[j], 0.0f);
    }
    __syncthreads();

    // ---- 128 -> 128 : quarter = 32 floats = 8 float4 ----
    {
        const float4* wr = reinterpret_cast<const float4*>(w3 + j * HD + q * 32);
        const float4* hv = reinterpret_cast<const float4*>(h1 + q * 32);
        float acc = dot_quarter<8>(wr, hv);
        acc += __shfl_xor_sync(0xFFFFFFFFu, acc, 1);
        acc += __shfl_xor_sync(0xFFFFFFFFu, acc, 2);
        if (q == 0) h2[j] = fmaxf(acc + b3[j], 0.0f);
    }
    __syncthreads();

    // ---- 128 -> 128 ----
    {
        const float4* wr = reinterpret_cast<const float4*>(w4 + j * HD + q * 32);
        const float4* hv = reinterpret_cast<const float4*>(h2 + q * 32);
        float acc = dot_quarter<8>(wr, hv);
        acc += __shfl_xor_sync(0xFFFFFFFFu, acc, 1);
        acc += __shfl_xor_sync(0xFFFFFFFFu, acc, 2);
        if (q == 0) h3[j] = fmaxf(acc + b4[j], 0.0f);
    }
    __syncthreads();

    // ---- 128 -> 12 head : run on 2 fully-converged warps (tid < 64),
    //      clamp j for dummy lanes so shfl masks stay legal. ----
    if (tid < 64) {
        const int jj = (j < NCH * NMIX) ? j : 0;
        const float4* wr = reinterpret_cast<const float4*>(w5 + jj * HD + q * 32);
        const float4* hv = reinterpret_cast<const float4*>(h3 + q * 32);
        float acc = dot_quarter<8>(wr, hv);
        acc += __shfl_xor_sync(0xFFFFFFFFu, acc, 1);
        acc += __shfl_xor_sync(0xFFFFFFFFu, acc, 2);
        if (q == 0 && j < NCH * NMIX)
            out[b * (NCH * NMIX) + j] = acc + b5[j];
    }
}

extern "C" void kernel_launch(void* const* d_in, const int* in_sizes, int n_in,
                              void* d_out, int out_size)
{
    (void)in_sizes; (void)n_in; (void)out_size;
    const float* xc   = (const float*)d_in[0];
    const float* yc   = (const float*)d_in[1];
    const float* mu   = (const float*)d_in[2];
    const float* istd = (const float*)d_in[3];
    const float* w1   = (const float*)d_in[4];
    const float* b1   = (const float*)d_in[5];
    const float* w2   = (const float*)d_in[6];
    const float* b2   = (const float*)d_in[7];
    const float* w3   = (const float*)d_in[8];
    const float* b3   = (const float*)d_in[9];
    const float* w4   = (const float*)d_in[10];
    const float* b4   = (const float*)d_in[11];
    const float* w5   = (const float*)d_in[12];
    const float* b5   = (const float*)d_in[13];
    float* out        = (float*)d_out;

    k1_feature<<<1536, 64>>>(xc, yc, mu, istd);
    k2a_layer1<<<384, 256>>>(yc, w1, b1);
    k2b_mlp<<<NB, 512>>>(w2, b2, w3, b3, w4, b4, w5, b5, out);
}

// round 13
// speedup vs baseline: 1.1278x; 1.1278x over previous
#include <cuda_runtime.h>
#include <math.h>

#define NB   8
#define ND   512
#define NDIM 2
#define NCH  3
#define NMIX 4
#define HD   128

typedef unsigned long long u64;

// feature: [b][a][k][m], m contiguous (float4-friendly)
__device__ float g_feat[NB * ND * NCH * NMIX];
// layer-1 partial sums: [b][k][j][quarter]
__device__ float g_h0p[NB * NCH * HD * 4];

__device__ __forceinline__ float ex2_approx(float x) {
    float r;
    asm("ex2.approx.ftz.f32 %0, %1;" : "=f"(r) : "f"(x));
    return r;
}
__device__ __forceinline__ u64 fma2(u64 a, u64 b, u64 c) {
    u64 d; asm("fma.rn.f32x2 %0, %1, %2, %3;" : "=l"(d) : "l"(a), "l"(b), "l"(c)); return d;
}
__device__ __forceinline__ u64 add2(u64 a, u64 b) {
    u64 d; asm("add.rn.f32x2 %0, %1, %2;" : "=l"(d) : "l"(a), "l"(b)); return d;
}
__device__ __forceinline__ u64 mul2(u64 a, u64 b) {
    u64 d; asm("mul.rn.f32x2 %0, %1, %2;" : "=l"(d) : "l"(a), "l"(b)); return d;
}
__device__ __forceinline__ u64 pack2(float lo, float hi) {
    u64 d; asm("mov.b64 %0, {%1, %2};" : "=l"(d) : "f"(lo), "f"(hi)); return d;
}
__device__ __forceinline__ void unpack2(u64 v, float& lo, float& hi) {
    asm("mov.b64 {%0, %1}, %2;" : "=f"(lo), "=f"(hi) : "l"(v));
}

// ---------------------------------------------------------------------------
// Kernel 1: fused pairwise SM-kernel + contraction.
// Grid: 96 combos (b,k,m) x 8 a-slices = 768 blocks, 256 threads.
// Block = 64 a-threads x 4 c-quarters; quarters reduced in smem at the end.
// ---------------------------------------------------------------------------
__global__ __launch_bounds__(256) void k1_feature(
    const float* __restrict__ xc, const float* __restrict__ yc,
    const float* __restrict__ mu, const float* __restrict__ istd)
{
    // per-c-pair SoA: sA={u0lo,u0hi,u1lo,u1hi}, sB={ezlo,ezhi,yclo,ychi}
    __shared__ float4 sA[256];
    __shared__ float4 sB[256];
    __shared__ float2 sY[256];
    __shared__ float  sred[4 * 64];

    const int bx    = blockIdx.x;
    const int slice = bx & 7;        // a slice of 64
    const int combo = bx >> 3;       // 0..95
    const int m     = combo & 3;
    const int bk    = combo >> 2;    // b*3+k
    const int k     = bk % 3;
    const int b     = bk / 3;

    const float AL2  = 19.739208802178716f * 1.4426950408889634f; // 0.5*(2pi)^2*log2e
    const float PI2f = 6.2831853071795864f;

    const float is0 = istd[m * 2 + 0], is1 = istd[m * 2 + 1];
    const float m0  = mu[m * 2 + 0],  m1  = mu[m * 2 + 1];

    const int tid = threadIdx.x;
    const int q   = tid >> 6;        // c-quarter 0..3
    const int t   = tid & 63;        // a within slice

    // ---- a-side loads early ----
    const int a  = slice * 64 + t;
    const int ai = b * ND + a;
    const float ax0 = xc[ai * 6 + k];
    const float ax1 = xc[ai * 6 + 3 + k];

    // ---- c-side precompute: 256 threads x 2 c's = all 512 ----
    float* Af = reinterpret_cast<float*>(sA);
    float* Bf = reinterpret_cast<float*>(sB);
    float* Yf = reinterpret_cast<float*>(sY);
#pragma unroll
    for (int cl = tid; cl < 512; cl += 256) {
        const int gi = b * ND + cl;
        float x0 = xc[gi * 6 + k];
        float x1 = xc[gi * 6 + 3 + k];
        float y  = yc[gi * 3 + k];
        float u0 = x0 * is0, u1 = x1 * is1;
        float e  = u0 * u0 + u1 * u1;
        float p  = x0 * m0 + x1 * m1;
        p -= rintf(p);                 // range-reduce for MUFU accuracy
        float s, cph;
        __sincosf(PI2f * p, &s, &cph);
        const int pr = cl >> 1, h = cl & 1;
        Af[pr * 4 + h]     = u0;
        Af[pr * 4 + 2 + h] = u1;
        Bf[pr * 4 + h]     = -AL2 * e;
        Bf[pr * 4 + 2 + h] = y * cph;
        Yf[pr * 2 + h]     = y * s;
    }

    // ---- a-side per-thread values (packed duplicates) ----
    float ua0 = ax0 * is0, ua1 = ax1 * is1;
    float wa0 = 2.0f * AL2 * ua0;
    float wa1 = 2.0f * AL2 * ua1;
    float base = -AL2 * (ua0 * ua0 + ua1 * ua1);   // total exp2 arg <= 0
    float p = ax0 * m0 + ax1 * m1;
    p -= rintf(p);
    float sa, ca;
    __sincosf(PI2f * p, &sa, &ca);

    const u64 wa0p  = pack2(wa0, wa0);
    const u64 wa1p  = pack2(wa1, wa1);
    const u64 basep = pack2(base, base);
    const u64 sap   = pack2(sa, sa);
    const u64 cap   = pack2(ca, ca);

    __syncthreads();

    const ulonglong2* Au = reinterpret_cast<const ulonglong2*>(sA);
    const ulonglong2* Bu = reinterpret_cast<const ulonglong2*>(sB);
    const u64*        Yu = reinterpret_cast<const u64*>(sY);

    const int i0 = q * 64;          // 64 c-pairs per quarter
    u64 acc = 0;                    // packed {acc_even, acc_odd}
#pragma unroll 8
    for (int i = i0; i < i0 + 64; i++) {
        ulonglong2 va = Au[i];      // u0 pair, u1 pair
        ulonglong2 vb = Bu[i];      // ez pair, yc pair
        u64 yp = Yu[i];             // ys pair
        u64 tt = fma2(wa0p, va.x, vb.x);
        tt = fma2(wa1p, va.y, tt);
        tt = add2(tt, basep);
        float tl, th;
        unpack2(tt, tl, th);
        u64 ep = pack2(ex2_approx(tl), ex2_approx(th));
        u64 qq = fma2(sap, yp, mul2(cap, vb.y));
        acc = fma2(ep, qq, acc);
    }
    float alo, ahi;
    unpack2(acc, alo, ahi);
    sred[tid] = alo + ahi;          // sred[q*64 + t]
    __syncthreads();

    if (tid < 64) {
        float total = sred[tid] + sred[64 + tid] + sred[128 + tid] + sred[192 + tid];
        const int aa = slice * 64 + tid;
        const int gi = (b * ND + aa) * 3 + k;
        total += 0.0001f * yc[gi];  // ZITTER * eye (diagonal c==a term)
        g_feat[gi * 4 + m] = total;
    }
}

// ---------------------------------------------------------------------------
// Kernel 2a: layer-1 + relu + partial mean. Block = (b, k, a-quarter).
// 96 blocks x 128 threads (one per j). Feature tile staged in smem ONCE,
// then broadcast-read by all threads. Writes partial sums [b][k][j][q].
// ---------------------------------------------------------------------------
__global__ __launch_bounds__(128) void k2a_layer1(
    const float* __restrict__ yc,
    const float* __restrict__ w1, const float* __restrict__ b1)
{
    __shared__ float4 sF[128];
    __shared__ float  sy[128];

    const int bx = blockIdx.x;
    const int q  = bx & 3;          // a-quarter
    const int bk = bx >> 2;
    const int k  = bk % 3;
    const int b  = bk / 3;
    const int tid = threadIdx.x;    // = j

    const float4* gF = reinterpret_cast<const float4*>(g_feat);
    const int a0 = q * 128;
    const int gi = (b * ND + a0 + tid) * 3 + k;
    sF[tid] = gF[gi];
    sy[tid] = yc[gi];
    __syncthreads();

    const int j = tid;
    const float wj0 = w1[j * 5 + 0], wj1 = w1[j * 5 + 1], wj2 = w1[j * 5 + 2];
    const float wj3 = w1[j * 5 + 3], wj4 = w1[j * 5 + 4], bj = b1[j];

    float acc = 0.0f;
#pragma unroll 4
    for (int i = 0; i < 128; i++) {
        float4 f = sF[i];
        float  y = sy[i];
        float v = fmaf(f.x, wj0,
                  fmaf(f.y, wj1,
                  fmaf(f.z, wj2,
                  fmaf(f.w, wj3,
                  fmaf(y,   wj4, bj)))));
        acc += fmaxf(v, 0.0f);
    }
    g_h0p[((b * NCH + k) * HD + j) * 4 + q] = acc;
}

// ---------------------------------------------------------------------------
// Kernel 2b: 3 hidden GEMVs + head. 8 blocks x 512 threads, 4 threads/output.
// ---------------------------------------------------------------------------
template <int N4>
__device__ __forceinline__ float dot_quarter(const float4* wr, const float4* hv) {
    float a0 = 0.0f, a1 = 0.0f;
#pragma unroll
    for (int i = 0; i < N4; i++) {
        float4 w = wr[i], h = hv[i];
        if (i & 1)
            a1 = fmaf(w.x, h.x, fmaf(w.y, h.y, fmaf(w.z, h.z, fmaf(w.w, h.w, a1))));
        else
            a0 = fmaf(w.x, h.x, fmaf(w.y, h.y, fmaf(w.z, h.z, fmaf(w.w, h.w, a0))));
    }
    return a0 + a1;
}

__global__ __launch_bounds__(512) void k2b_mlp(
    const float* __restrict__ w2, const float* __restrict__ b2,
    const float* __restrict__ w3, const float* __restrict__ b3,
    const float* __restrict__ w4, const float* __restrict__ b4,
    const float* __restrict__ w5, const float* __restrict__ b5,
    float* __restrict__ out)
{
    __shared__ __align__(16) float h0[NCH * HD];
    __shared__ __align__(16) float h1[HD];
    __shared__ __align__(16) float h2[HD];
    __shared__ __align__(16) float h3[HD];

    const int b   = blockIdx.x;
    const int tid = threadIdx.x;
    const int j   = tid >> 2;
    const int q   = tid & 3;

    // sum the 4 a-quarter partials, apply 1/ND mean
    {
        const float4* gp = reinterpret_cast<const float4*>(g_h0p);
        if (tid < NCH * HD) {
            float4 p = gp[b * (NCH * HD) + tid];
            h0[tid] = (p.x + p.y + p.z + p.w) * (1.0f / (float)ND);
        }
    }
    __syncthreads();

    // ---- 384 -> 128 : quarter = 96 floats = 24 float4 ----
    {
        const float4* wr = reinterpret_cast<const float4*>(w2 + j * (NCH * HD) + q * 96);
        const float4* hv = reinterpret_cast<const float4*>(h0 + q * 96);
        float acc = dot_quarter<24>(wr, hv);
        acc += __shfl_xor_sync(0xFFFFFFFFu, acc, 1);
        acc += __shfl_xor_sync(0xFFFFFFFFu, acc, 2);
        if (q == 0) h1[j] = fmaxf(acc + b2[j], 0.0f);
    }
    __syncthreads();

    // ---- 128 -> 128 ----
    {
        const float4* wr = reinterpret_cast<const float4*>(w3 + j * HD + q * 32);
        const float4* hv = reinterpret_cast<const float4*>(h1 + q * 32);
        float acc = dot_quarter<8>(wr, hv);
        acc += __shfl_xor_sync(0xFFFFFFFFu, acc, 1);
        acc += __shfl_xor_sync(0xFFFFFFFFu, acc, 2);
        if (q == 0) h2[j] = fmaxf(acc + b3[j], 0.0f);
    }
    __syncthreads();

    // ---- 128 -> 128 ----
    {
        const float4* wr = reinterpret_cast<const float4*>(w4 + j * HD + q * 32);
        const float4* hv = reinterpret_cast<const float4*>(h2 + q * 32);
        float acc = dot_quarter<8>(wr, hv);
        acc += __shfl_xor_sync(0xFFFFFFFFu, acc, 1);
        acc += __shfl_xor_sync(0xFFFFFFFFu, acc, 2);
        if (q == 0) h3[j] = fmaxf(acc + b4[j], 0.0f);
    }
    __syncthreads();

    // ---- 128 -> 12 head : two fully-converged warps ----
    if (tid < 64) {
        const int jj = (j < NCH * NMIX) ? j : 0;
        const float4* wr = reinterpret_cast<const float4*>(w5 + jj * HD + q * 32);
        const float4* hv = reinterpret_cast<const float4*>(h3 + q * 32);
        float acc = dot_quarter<8>(wr, hv);
        acc += __shfl_xor_sync(0xFFFFFFFFu, acc, 1);
        acc += __shfl_xor_sync(0xFFFFFFFFu, acc, 2);
        if (q == 0 && j < NCH * NMIX)
            out[b * (NCH * NMIX) + j] = acc + b5[j];
    }
}

extern "C" void kernel_launch(void* const* d_in, const int* in_sizes, int n_in,
                              void* d_out, int out_size)
{
    (void)in_sizes; (void)n_in; (void)out_size;
    const float* xc   = (const float*)d_in[0];
    const float* yc   = (const float*)d_in[1];
    const float* mu   = (const float*)d_in[2];
    const float* istd = (const float*)d_in[3];
    const float* w1   = (const float*)d_in[4];
    const float* b1   = (const float*)d_in[5];
    const float* w2   = (const float*)d_in[6];
    const float* b2   = (const float*)d_in[7];
    const float* w3   = (const float*)d_in[8];
    const float* b3   = (const float*)d_in[9];
    const float* w4   = (const float*)d_in[10];
    const float* b4   = (const float*)d_in[11];
    const float* w5   = (const float*)d_in[12];
    const float* b5   = (const float*)d_in[13];
    float* out        = (float*)d_out;

    k1_feature<<<768, 256>>>(xc, yc, mu, istd);
    k2a_layer1<<<NB * NCH * 4, 128>>>(yc, w1, b1);
    k2b_mlp<<<NB, 512>>>(w2, b2, w3, b3, w4, b4, w5, b5, out);
}

// round 15
// speedup vs baseline: 1.1464x; 1.0165x over previous
#include <cuda_runtime.h>
#include <math.h>

#define NB   8
#define ND   512
#define NDIM 2
#define NCH  3
#define NMIX 4
#define HD   128

typedef unsigned long long u64;

// feature: [b][a][k][m], m contiguous (float4-friendly)
__device__ float g_feat[NB * ND * NCH * NMIX];
// layer-1 partial sums: [b][k][j][quarter]
__device__ float g_h0p[NB * NCH * HD * 4];

__device__ __forceinline__ float ex2_approx(float x) {
    float r;
    asm("ex2.approx.ftz.f32 %0, %1;" : "=f"(r) : "f"(x));
    return r;
}
__device__ __forceinline__ u64 fma2(u64 a, u64 b, u64 c) {
    u64 d; asm("fma.rn.f32x2 %0, %1, %2, %3;" : "=l"(d) : "l"(a), "l"(b), "l"(c)); return d;
}
__device__ __forceinline__ u64 add2(u64 a, u64 b) {
    u64 d; asm("add.rn.f32x2 %0, %1, %2;" : "=l"(d) : "l"(a), "l"(b)); return d;
}
__device__ __forceinline__ u64 mul2(u64 a, u64 b) {
    u64 d; asm("mul.rn.f32x2 %0, %1, %2;" : "=l"(d) : "l"(a), "l"(b)); return d;
}
__device__ __forceinline__ u64 pack2(float lo, float hi) {
    u64 d; asm("mov.b64 %0, {%1, %2};" : "=l"(d) : "f"(lo), "f"(hi)); return d;
}
__device__ __forceinline__ void unpack2(u64 v, float& lo, float& hi) {
    asm("mov.b64 {%0, %1}, %2;" : "=f"(lo), "=f"(hi) : "l"(v));
}

// ---------------------------------------------------------------------------
// Kernel 1: fused pairwise SM-kernel + contraction, 4-a batching.
// Grid: 96 combos (b,k,m) x 8 a-slices = 768 blocks, 64 threads.
// Thread (t = tid&15, q = tid>>4): owns 4 a's {slice*64 + t*4 + s} and one
// c-quarter. Each LDS triple feeds 4 accumulators (LDS count /4 vs R13).
// ---------------------------------------------------------------------------
__global__ __launch_bounds__(64) void k1_feature(
    const float* __restrict__ xc, const float* __restrict__ yc,
    const float* __restrict__ mu, const float* __restrict__ istd)
{
    // per-c-pair SoA: sA={u0lo,u0hi,u1lo,u1hi}, sB={ezlo,ezhi,yclo,ychi}
    __shared__ float4 sA[256];
    __shared__ float4 sB[256];
    __shared__ float2 sY[256];
    __shared__ float4 sred[4 * 16];   // [q][t] -> 4 stream partials

    const int bx    = blockIdx.x;
    const int slice = bx & 7;        // a slice of 64
    const int combo = bx >> 3;       // 0..95
    const int m     = combo & 3;
    const int bk    = combo >> 2;    // b*3+k
    const int k     = bk % 3;
    const int b     = bk / 3;

    const float AL2  = 19.739208802178716f * 1.4426950408889634f; // 0.5*(2pi)^2*log2e
    const float PI2f = 6.2831853071795864f;

    const float is0 = istd[m * 2 + 0], is1 = istd[m * 2 + 1];
    const float m0  = mu[m * 2 + 0],  m1  = mu[m * 2 + 1];

    const int tid = threadIdx.x;     // 0..63
    const int q   = tid >> 4;        // c-quarter 0..3
    const int t   = tid & 15;        // a-group 0..15

    // ---- c-side precompute: 64 threads x 8 c's = all 512 ----
    float* Af = reinterpret_cast<float*>(sA);
    float* Bf = reinterpret_cast<float*>(sB);
    float* Yf = reinterpret_cast<float*>(sY);
#pragma unroll
    for (int cl = tid; cl < 512; cl += 64) {
        const int gi = b * ND + cl;
        float x0 = xc[gi * 6 + k];
        float x1 = xc[gi * 6 + 3 + k];
        float y  = yc[gi * 3 + k];
        float u0 = x0 * is0, u1 = x1 * is1;
        float e  = u0 * u0 + u1 * u1;
        float p  = x0 * m0 + x1 * m1;
        p -= rintf(p);                 // range-reduce for MUFU accuracy
        float s, cph;
        __sincosf(PI2f * p, &s, &cph);
        const int pr = cl >> 1, h = cl & 1;
        Af[pr * 4 + h]     = u0;
        Af[pr * 4 + 2 + h] = u1;
        Bf[pr * 4 + h]     = -AL2 * e;
        Bf[pr * 4 + 2 + h] = y * cph;
        Yf[pr * 2 + h]     = y * s;
    }

    // ---- a-side per-thread values for 4 streams ----
    u64 wa0p[4], wa1p[4], basep[4], sap[4], cap[4];
#pragma unroll
    for (int s = 0; s < 4; s++) {
        const int a  = slice * 64 + t * 4 + s;
        const int ai = b * ND + a;
        float ax0 = xc[ai * 6 + k];
        float ax1 = xc[ai * 6 + 3 + k];
        float ua0 = ax0 * is0, ua1 = ax1 * is1;
        float wa0 = 2.0f * AL2 * ua0;
        float wa1 = 2.0f * AL2 * ua1;
        float base = -AL2 * (ua0 * ua0 + ua1 * ua1);   // total exp2 arg <= 0
        float p = ax0 * m0 + ax1 * m1;
        p -= rintf(p);
        float sa, ca;
        __sincosf(PI2f * p, &sa, &ca);
        wa0p[s]  = pack2(wa0, wa0);
        wa1p[s]  = pack2(wa1, wa1);
        basep[s] = pack2(base, base);
        sap[s]   = pack2(sa, sa);
        cap[s]   = pack2(ca, ca);
    }

    __syncthreads();

    const ulonglong2* Au = reinterpret_cast<const ulonglong2*>(sA);
    const ulonglong2* Bu = reinterpret_cast<const ulonglong2*>(sB);
    const u64*        Yu = reinterpret_cast<const u64*>(sY);

    const int i0 = q * 64;          // 64 c-pairs per quarter
    u64 acc[4] = {0, 0, 0, 0};      // packed {acc_even, acc_odd} per stream
#pragma unroll 4
    for (int i = i0; i < i0 + 64; i++) {
        ulonglong2 va = Au[i];      // u0 pair, u1 pair
        ulonglong2 vb = Bu[i];      // ez pair, yc pair
        u64 yp = Yu[i];             // ys pair
#pragma unroll
        for (int s = 0; s < 4; s++) {
            u64 tt = fma2(wa0p[s], va.x, vb.x);
            tt = fma2(wa1p[s], va.y, tt);
            tt = add2(tt, basep[s]);
            float tl, th;
            unpack2(tt, tl, th);
            u64 ep = pack2(ex2_approx(tl), ex2_approx(th));
            u64 qq = fma2(sap[s], yp, mul2(cap[s], vb.y));
            acc[s] = fma2(ep, qq, acc[s]);
        }
    }
    float4 r;
    { float lo, hi;
      unpack2(acc[0], lo, hi); r.x = lo + hi;
      unpack2(acc[1], lo, hi); r.y = lo + hi;
      unpack2(acc[2], lo, hi); r.z = lo + hi;
      unpack2(acc[3], lo, hi); r.w = lo + hi; }
    sred[q * 16 + t] = r;
    __syncthreads();

    if (tid < 16) {
        float4 r0 = sred[tid];
        float4 r1 = sred[16 + tid];
        float4 r2 = sred[32 + tid];
        float4 r3 = sred[48 + tid];
        float tot[4] = { r0.x + r1.x + r2.x + r3.x,
                         r0.y + r1.y + r2.y + r3.y,
                         r0.z + r1.z + r2.z + r3.z,
                         r0.w + r1.w + r2.w + r3.w };
#pragma unroll
        for (int s = 0; s < 4; s++) {
            const int a  = slice * 64 + tid * 4 + s;
            const int gi = (b * ND + a) * 3 + k;
            g_feat[gi * 4 + m] = tot[s] + 0.0001f * yc[gi];  // ZITTER * eye
        }
    }
}

// ---------------------------------------------------------------------------
// Kernel 2a: layer-1 + relu + partial mean. Block = (b, k, a-quarter).
// 96 blocks x 128 threads (one per j). Feature tile staged in smem ONCE.
// (byte-identical to R13 for attribution)
// ---------------------------------------------------------------------------
__global__ __launch_bounds__(128) void k2a_layer1(
    const float* __restrict__ yc,
    const float* __restrict__ w1, const float* __restrict__ b1)
{
    __shared__ float4 sF[128];
    __shared__ float  sy[128];

    const int bx = blockIdx.x;
    const int q  = bx & 3;          // a-quarter
    const int bk = bx >> 2;
    const int k  = bk % 3;
    const int b  = bk / 3;
    const int tid = threadIdx.x;    // = j

    const float4* gF = reinterpret_cast<const float4*>(g_feat);
    const int a0 = q * 128;
    const int gi = (b * ND + a0 + tid) * 3 + k;
    sF[tid] = gF[gi];
    sy[tid] = yc[gi];
    __syncthreads();

    const int j = tid;
    const float wj0 = w1[j * 5 + 0], wj1 = w1[j * 5 + 1], wj2 = w1[j * 5 + 2];
    const float wj3 = w1[j * 5 + 3], wj4 = w1[j * 5 + 4], bj = b1[j];

    float acc = 0.0f;
#pragma unroll 4
    for (int i = 0; i < 128; i++) {
        float4 f = sF[i];
        float  y = sy[i];
        float v = fmaf(f.x, wj0,
                  fmaf(f.y, wj1,
                  fmaf(f.z, wj2,
                  fmaf(f.w, wj3,
                  fmaf(y,   wj4, bj)))));
        acc += fmaxf(v, 0.0f);
    }
    g_h0p[((b * NCH + k) * HD + j) * 4 + q] = acc;
}

// ---------------------------------------------------------------------------
// Kernel 2b: 3 hidden GEMVs + head. 8 blocks x 512 threads, 4 threads/output.
// (byte-identical to R13 for attribution)
// ---------------------------------------------------------------------------
template <int N4>
__device__ __forceinline__ float dot_quarter(const float4* wr, const float4* hv) {
    float a0 = 0.0f, a1 = 0.0f;
#pragma unroll
    for (int i = 0; i < N4; i++) {
        float4 w = wr[i], h = hv[i];
        if (i & 1)
            a1 = fmaf(w.x, h.x, fmaf(w.y, h.y, fmaf(w.z, h.z, fmaf(w.w, h.w, a1))));
        else
            a0 = fmaf(w.x, h.x, fmaf(w.y, h.y, fmaf(w.z, h.z, fmaf(w.w, h.w, a0))));
    }
    return a0 + a1;
}

__global__ __launch_bounds__(512) void k2b_mlp(
    const float* __restrict__ w2, const float* __restrict__ b2,
    const float* __restrict__ w3, const float* __restrict__ b3,
    const float* __restrict__ w4, const float* __restrict__ b4,
    const float* __restrict__ w5, const float* __restrict__ b5,
    float* __restrict__ out)
{
    __shared__ __align__(16) float h0[NCH * HD];
    __shared__ __align__(16) float h1[HD];
    __shared__ __align__(16) float h2[HD];
    __shared__ __align__(16) float h3[HD];

    const int b   = blockIdx.x;
    const int tid = threadIdx.x;
    const int j   = tid >> 2;
    const int q   = tid & 3;

    // sum the 4 a-quarter partials, apply 1/ND mean
    {
        const float4* gp = reinterpret_cast<const float4*>(g_h0p);
        if (tid < NCH * HD) {
            float4 p = gp[b * (NCH * HD) + tid];
            h0[tid] = (p.x + p.y + p.z + p.w) * (1.0f / (float)ND);
        }
    }
    __syncthreads();

    // ---- 384 -> 128 : quarter = 96 floats = 24 float4 ----
    {
        const float4* wr = reinterpret_cast<const float4*>(w2 + j * (NCH * HD) + q * 96);
        const float4* hv = reinterpret_cast<const float4*>(h0 + q * 96);
        float acc = dot_quarter<24>(wr, hv);
        acc += __shfl_xor_sync(0xFFFFFFFFu, acc, 1);
        acc += __shfl_xor_sync(0xFFFFFFFFu, acc, 2);
        if (q == 0) h1[j] = fmaxf(acc + b2[j], 0.0f);
    }
    __syncthreads();

    // ---- 128 -> 128 ----
    {
        const float4* wr = reinterpret_cast<const float4*>(w3 + j * HD + q * 32);
        const float4* hv = reinterpret_cast<const float4*>(h1 + q * 32);
        float acc = dot_quarter<8>(wr, hv);
        acc += __shfl_xor_sync(0xFFFFFFFFu, acc, 1);
        acc += __shfl_xor_sync(0xFFFFFFFFu, acc, 2);
        if (q == 0) h2[j] = fmaxf(acc + b3[j], 0.0f);
    }
    __syncthreads();

    // ---- 128 -> 128 ----
    {
        const float4* wr = reinterpret_cast<const float4*>(w4 + j * HD + q * 32);
        const float4* hv = reinterpret_cast<const float4*>(h2 + q * 32);
        float acc = dot_quarter<8>(wr, hv);
        acc += __shfl_xor_sync(0xFFFFFFFFu, acc, 1);
        acc += __shfl_xor_sync(0xFFFFFFFFu, acc, 2);
        if (q == 0) h3[j] = fmaxf(acc + b4[j], 0.0f);
    }
    __syncthreads();

    // ---- 128 -> 12 head : two fully-converged warps ----
    if (tid < 64) {
        const int jj = (j < NCH * NMIX) ? j : 0;
        const float4* wr = reinterpret_cast<const float4*>(w5 + jj * HD + q * 32);
        const float4* hv = reinterpret_cast<const float4*>(h3 + q * 32);
        float acc = dot_quarter<8>(wr, hv);
        acc += __shfl_xor_sync(0xFFFFFFFFu, acc, 1);
        acc += __shfl_xor_sync(0xFFFFFFFFu, acc, 2);
        if (q == 0 && j < NCH * NMIX)
            out[b * (NCH * NMIX) + j] = acc + b5[j];
    }
}

extern "C" void kernel_launch(void* const* d_in, const int* in_sizes, int n_in,
                              void* d_out, int out_size)
{
    (void)in_sizes; (void)n_in; (void)out_size;
    const float* xc   = (const float*)d_in[0];
    const float* yc   = (const float*)d_in[1];
    const float* mu   = (const float*)d_in[2];
    const float* istd = (const float*)d_in[3];
    const float* w1   = (const float*)d_in[4];
    const float* b1   = (const float*)d_in[5];
    const float* w2   = (const float*)d_in[6];
    const float* b2   = (const float*)d_in[7];
    const float* w3   = (const float*)d_in[8];
    const float* b3   = (const float*)d_in[9];
    const float* w4   = (const float*)d_in[10];
    const float* b4   = (const float*)d_in[11];
    const float* w5   = (const float*)d_in[12];
    const float* b5   = (const float*)d_in[13];
    float* out        = (float*)d_out;

    k1_feature<<<768, 64>>>(xc, yc, mu, istd);
    k2a_layer1<<<NB * NCH * 4, 128>>>(yc, w1, b1);
    k2b_mlp<<<NB, 512>>>(w2, b2, w3, b3, w4, b4, w5, b5, out);
}